// round 8
// baseline (speedup 1.0000x reference)
#include <cuda_runtime.h>
#include <cstdint>
#include <math.h>

// Problem constants
#define BB 64
#define SS 64
#define TT 21
#define DD 512
#define VV 32000
#define BT (BB*TT)        // 1344
#define NTILE (VV/64)     // 500

// ---------------- static device scratch ----------------
__device__ float g_cat[BB*640];        // [encode_hidden | style_feature]
__device__ float g_inp2[BB*1024];      // [context | h]
__device__ float g_gates[BB*2048];
__device__ float g_c[BB*512];
__device__ float g_emb[BT*512];        // emb_table[decoder_input]
__device__ float g_xproj[BT*2048];     // emb @ W_ih_emb^T + b_ih + b_hh
__device__ float g_wcomb[2048*1024];   // [W_ih_ctx | W_hh]
__device__ float g_biassum[2048];
__device__ float g_E2[BB*SS*512];      // enc @ attn_W^T  (scores = E2 . h)
__device__ float g_outs[BT*512];       // LSTM hidden outputs
__device__ float g_pmax[BT*NTILE];
__device__ float g_psum[BT*NTILE];
__device__ float g_lab[BT];
__device__ float g_nll[BT];

// ---------------- packed f32x2 helpers (Blackwell FFMA2) ----------------
__device__ __forceinline__ double pk2(float lo, float hi) {
    double d;
    asm("mov.b64 %0, {%1, %2};" : "=d"(d) : "f"(lo), "f"(hi));
    return d;
}
__device__ __forceinline__ void upk2(double v, float& lo, float& hi) {
    asm("mov.b64 {%0, %1}, %2;" : "=f"(lo), "=f"(hi) : "d"(v));
}
__device__ __forceinline__ void fma2(double& d, double a, double b) {
    asm("fma.rn.f32x2 %0, %1, %2, %0;" : "+d"(d) : "d"(a), "d"(b));
}

// Shared tile geometry:
//   Asd: 32 x 132 floats, A values duplicated: Asd[k][2m]=Asd[k][2m+1]=A[m]
//        row stride 132*4=528 B (multiple of 16) -> LDS.128 of (a_i,a_i),(a_{i+1},a_{i+1})
//   Bs : 32 x 68 floats, Bs[k][n] (row stride 272 B, multiple of 16)
#define ASD_LD 132
#define BS_LD 68

// Load A 64x32 tile duplicated. src row-major with leading dim ld.
__device__ __forceinline__ void load_tile_dupA(float* __restrict__ dst,
    const float* __restrict__ src, int ld, int row0, int k0, int tid)
{
#pragma unroll
    for (int i = 0; i < 2; i++) {
        int e = tid + i * 256;          // 512 work items, each a float4
        int m = e >> 3;                 // 0..63
        int kq = (e & 7) * 4;           // 0..28
        float4 v = *reinterpret_cast<const float4*>(
            &src[(size_t)(row0 + m) * ld + k0 + kq]);
        double* d0 = reinterpret_cast<double*>(&dst[(kq + 0) * ASD_LD + 2 * m]);
        double* d1 = reinterpret_cast<double*>(&dst[(kq + 1) * ASD_LD + 2 * m]);
        double* d2 = reinterpret_cast<double*>(&dst[(kq + 2) * ASD_LD + 2 * m]);
        double* d3 = reinterpret_cast<double*>(&dst[(kq + 3) * ASD_LD + 2 * m]);
        *d0 = pk2(v.x, v.x);
        *d1 = pk2(v.y, v.y);
        *d2 = pk2(v.z, v.z);
        *d3 = pk2(v.w, v.w);
    }
}

// Load B 64x32 tile (B is (N,K) row-major): Bs[k][n] = B[(bn+n)*ldb + k0+k]
__device__ __forceinline__ void load_tile_B(float* __restrict__ dst,
    const float* __restrict__ src, int ld, int row0, int k0, int tid)
{
#pragma unroll
    for (int i = 0; i < 2; i++) {
        int e = tid + i * 256;
        int n = e >> 3;                 // 0..63
        int kq = (e & 7) * 4;
        float4 v = *reinterpret_cast<const float4*>(
            &src[(size_t)(row0 + n) * ld + k0 + kq]);
        dst[(kq + 0) * BS_LD + n] = v.x;
        dst[(kq + 1) * BS_LD + n] = v.y;
        dst[(kq + 2) * BS_LD + n] = v.z;
        dst[(kq + 3) * BS_LD + n] = v.w;
    }
}

// Inner product over one 32-k chunk: 4x4 tile per thread via 8 FFMA2 / k
__device__ __forceinline__ void mm_chunk(double (&acc2)[4][2],
    const float* __restrict__ Asd, const float* __restrict__ Bs,
    int tm, int tn)
{
#pragma unroll
    for (int k = 0; k < 32; k++) {
        double2 Alo = *reinterpret_cast<const double2*>(&Asd[k * ASD_LD + 2 * tm]);
        double2 Ahi = *reinterpret_cast<const double2*>(&Asd[k * ASD_LD + 2 * tm + 4]);
        double2 Bv  = *reinterpret_cast<const double2*>(&Bs[k * BS_LD + tn]);
        fma2(acc2[0][0], Alo.x, Bv.x); fma2(acc2[0][1], Alo.x, Bv.y);
        fma2(acc2[1][0], Alo.y, Bv.x); fma2(acc2[1][1], Alo.y, Bv.y);
        fma2(acc2[2][0], Ahi.x, Bv.x); fma2(acc2[2][1], Ahi.x, Bv.y);
        fma2(acc2[3][0], Ahi.y, Bv.x); fma2(acc2[3][1], Ahi.y, Bv.y);
    }
}

// ---------------- tiled fp32 GEMM: C[M,N] (+)= A[M,K] @ B[N,K]^T ----------------
// ATOMIC: atomicAdd into C (split-K; C pre-inited; bias/addf ignored).
// kbeg = blockIdx.z*klen. Block tile 64x64, 256 threads.
template<bool ATOMIC>
__global__ void gemm_kernel(int klen,
                            const float* __restrict__ A, int lda,
                            const float* __restrict__ B, int ldb,
                            float* __restrict__ C, int ldc,
                            const float* __restrict__ bias,
                            const float* __restrict__ addf, int ldd)
{
    __shared__ float Asd[32 * ASD_LD];
    __shared__ float Bs[32 * BS_LD];
    const int bm = blockIdx.y * 64;
    const int bn = blockIdx.x * 64;
    const int kbeg = blockIdx.z * klen;
    const int tid = threadIdx.x;
    const int tm = (tid >> 4) << 2;
    const int tn = (tid & 15) << 2;
    double acc2[4][2] = {};

    for (int k0 = kbeg; k0 < kbeg + klen; k0 += 32) {
        load_tile_dupA(Asd, A, lda, bm, k0, tid);
        load_tile_B(Bs, B, ldb, bn, k0, tid);
        __syncthreads();
        mm_chunk(acc2, Asd, Bs, tm, tn);
        __syncthreads();
    }

    float acc[4][4];
#pragma unroll
    for (int i = 0; i < 4; i++) {
        upk2(acc2[i][0], acc[i][0], acc[i][1]);
        upk2(acc2[i][1], acc[i][2], acc[i][3]);
    }

    if (ATOMIC) {
#pragma unroll
        for (int i = 0; i < 4; i++) {
            size_t ro = (size_t)(bm + tm + i);
#pragma unroll
            for (int j = 0; j < 4; j++)
                atomicAdd(&C[ro * ldc + bn + tn + j], acc[i][j]);
        }
    } else {
#pragma unroll
        for (int i = 0; i < 4; i++) {
            size_t ro = (size_t)(bm + tm + i);
#pragma unroll
            for (int j = 0; j < 4; j++) {
                float v = acc[i][j];
                int n = bn + tn + j;
                if (bias) v += bias[n];
                if (addf) v += addf[ro * ldd + n];
                C[ro * ldc + n] = v;
            }
        }
    }
}

// ---------------- projection GEMM fused with per-tile logsumexp partials ----------------
__global__ void proj_lse_kernel(const float* __restrict__ Bw, const float* __restrict__ pb)
{
    __shared__ float Asd[32 * ASD_LD];
    __shared__ float Bs[32 * BS_LD];
    const int bm = blockIdx.y * 64;
    const int bn = blockIdx.x * 64;
    const int tid = threadIdx.x;
    const int tm = (tid >> 4) << 2;
    const int tn = (tid & 15) << 2;
    double acc2[4][2] = {};
    const float* Aouts = g_outs;

    for (int k0 = 0; k0 < 512; k0 += 32) {
        load_tile_dupA(Asd, Aouts, 512, bm, k0, tid);
        load_tile_B(Bs, Bw, 512, bn, k0, tid);
        __syncthreads();
        mm_chunk(acc2, Asd, Bs, tm, tn);
        __syncthreads();
    }

    float acc[4][4];
#pragma unroll
    for (int i = 0; i < 4; i++) {
        upk2(acc2[i][0], acc[i][0], acc[i][1]);
        upk2(acc2[i][1], acc[i][2], acc[i][3]);
    }

    float bj[4];
#pragma unroll
    for (int j = 0; j < 4; j++) bj[j] = pb[bn + tn + j];
#pragma unroll
    for (int i = 0; i < 4; i++)
#pragma unroll
        for (int j = 0; j < 4; j++) acc[i][j] += bj[j];

    // per output-row reduction across the 16 threads of the row group
#pragma unroll
    for (int i = 0; i < 4; i++) {
        float m = fmaxf(fmaxf(acc[i][0], acc[i][1]), fmaxf(acc[i][2], acc[i][3]));
#pragma unroll
        for (int o = 8; o; o >>= 1) m = fmaxf(m, __shfl_xor_sync(0xffffffffu, m, o));
        float se = expf(acc[i][0] - m) + expf(acc[i][1] - m)
                 + expf(acc[i][2] - m) + expf(acc[i][3] - m);
#pragma unroll
        for (int o = 8; o; o >>= 1) se += __shfl_xor_sync(0xffffffffu, se, o);
        if ((tid & 15) == 0) {
            int row = bm + tm + i;
            g_pmax[(size_t)row * NTILE + blockIdx.x] = m;
            g_psum[(size_t)row * NTILE + blockIdx.x] = se;
        }
    }
}

// ---------------- fused pointwise(t-1) + attention(t) ----------------
__global__ void pwattn_kernel(const float* __restrict__ enc, int t)
{
    __shared__ float hs[512];
    __shared__ float sc[64];
    __shared__ float s_inv;
    const int b = blockIdx.x, tid = threadIdx.x;

    if (t > 0) {
        const int gb = b * 2048;
#pragma unroll
        for (int u = 0; u < 2; u++) {
            int j = tid + u * 256;
            float gi = g_gates[gb + j];
            float gf = g_gates[gb + 512 + j];
            float gg = g_gates[gb + 1024 + j];
            float go = g_gates[gb + 1536 + j];
            float c = g_c[b * 512 + j];
            float si = 1.f / (1.f + expf(-gi));
            float sf = 1.f / (1.f + expf(-gf));
            float so = 1.f / (1.f + expf(-go));
            c = sf * c + si * tanhf(gg);
            g_c[b * 512 + j] = c;
            float h = so * tanhf(c);
            g_outs[(size_t)(b * TT + (t - 1)) * 512 + j] = h;
            g_inp2[b * 1024 + 512 + j] = h;
            hs[j] = h;
        }
    } else {
        hs[tid]       = g_inp2[b * 1024 + 512 + tid];
        hs[tid + 256] = g_inp2[b * 1024 + 768 + tid];
    }
    __syncthreads();

    // init gates = xproj[:, t, :] for the split-K atomic GEMM
    {
        size_t xo = (size_t)(b * TT + t) * 2048;
#pragma unroll
        for (int i = 0; i < 8; i++)
            g_gates[b * 2048 + tid + i * 256] = g_xproj[xo + tid + i * 256];
    }

    const int w = tid >> 5, lane = tid & 31;
    const float* E2b = g_E2 + (size_t)b * SS * 512;
    for (int s = w; s < SS; s += 8) {
        const float* er = E2b + (size_t)s * 512;
        float a = 0.f;
        for (int k = lane; k < 512; k += 32) a += hs[k] * er[k];
#pragma unroll
        for (int o = 16; o; o >>= 1) a += __shfl_xor_sync(0xffffffffu, a, o);
        if (lane == 0) sc[s] = a;
    }
    __syncthreads();

    if (w == 0) {
        float v0 = sc[lane], v1 = sc[lane + 32];
        float m = fmaxf(v0, v1);
#pragma unroll
        for (int o = 16; o; o >>= 1) m = fmaxf(m, __shfl_xor_sync(0xffffffffu, m, o));
        float e0 = expf(v0 - m), e1 = expf(v1 - m);
        float ssm = e0 + e1;
#pragma unroll
        for (int o = 16; o; o >>= 1) ssm += __shfl_xor_sync(0xffffffffu, ssm, o);
        sc[lane] = e0; sc[lane + 32] = e1;
        if (lane == 0) s_inv = 1.f / ssm;
    }
    __syncthreads();

    float inv = s_inv;
    const float* eb = enc + (size_t)b * SS * DD;
    for (int d = tid; d < DD; d += 256) {
        float a = 0.f;
#pragma unroll 8
        for (int s = 0; s < SS; s++) a += sc[s] * eb[(size_t)s * DD + d];
        g_inp2[b * 1024 + d] = a * inv;
    }
}

// final pointwise (produces outs[T-1])
__global__ void pw_final_kernel()
{
    const int b = blockIdx.x, j = threadIdx.x;
    const int gb = b * 2048;
    float gi = g_gates[gb + j];
    float gf = g_gates[gb + 512 + j];
    float gg = g_gates[gb + 1024 + j];
    float go = g_gates[gb + 1536 + j];
    float c = g_c[b * 512 + j];
    float si = 1.f / (1.f + expf(-gi));
    float sf = 1.f / (1.f + expf(-gf));
    float so = 1.f / (1.f + expf(-go));
    c = sf * c + si * tanhf(gg);
    float h = so * tanhf(c);
    g_outs[(size_t)(b * TT + TT - 1) * 512 + j] = h;
}

// ---------------- one-time prep ----------------
__global__ void prep_small_kernel(const float* __restrict__ eh, const float* __restrict__ st,
                                  const float* __restrict__ bih, const float* __restrict__ bhh)
{
    int i = blockIdx.x * blockDim.x + threadIdx.x;
    if (i < BB * 640) {
        int b = i / 640, j = i - b * 640;
        g_cat[i] = (j < 512) ? eh[b * 512 + j] : st[b * 512 + 384 + (j - 512)];
    } else if (i < BB * 640 + 2048) {
        int j = i - BB * 640;
        g_biassum[j] = bih[j] + bhh[j];
    } else if (i < BB * 640 + 2048 + BB * 512) {
        g_c[i - (BB * 640 + 2048)] = 0.f;
    }
}

__global__ void wcomb_kernel(const float* __restrict__ wih, const float* __restrict__ whh)
{
    int i = blockIdx.x * blockDim.x + threadIdx.x;
    int r = i >> 10, c = i & 1023;
    g_wcomb[i] = (c < 512) ? wih[(size_t)r * 1024 + c] : whh[(size_t)r * 512 + (c - 512)];
}

__global__ void embed_kernel(const int* __restrict__ di, const float* __restrict__ et)
{
    int row = blockIdx.x, tid = threadIdx.x;
    int idx = di[row];
    g_emb[(size_t)row * 512 + tid] = et[(size_t)idx * 512 + tid];
}

// ---------------- loss ----------------
__global__ void lablogit_kernel(const int* __restrict__ lab, const float* __restrict__ pw,
                                const float* __restrict__ pb)
{
    int gt = blockIdx.x * blockDim.x + threadIdx.x;
    int w = gt >> 5, lane = gt & 31;
    if (w >= BT) return;
    int l = lab[w];
    const float* o  = g_outs + (size_t)w * 512;
    const float* wr = pw + (size_t)l * 512;
    float a = 0.f;
    for (int k = lane; k < 512; k += 32) a += o[k] * wr[k];
#pragma unroll
    for (int off = 16; off; off >>= 1) a += __shfl_xor_sync(0xffffffffu, a, off);
    if (lane == 0) g_lab[w] = a + pb[l];
}

__global__ void loss_row_kernel(const int* __restrict__ lab)
{
    __shared__ float red[128];
    const int r = blockIdx.x, tid = threadIdx.x;
    const float* pm = g_pmax + (size_t)r * NTILE;
    const float* ps = g_psum + (size_t)r * NTILE;
    float m = -1e30f;
    for (int j = tid; j < NTILE; j += 128) m = fmaxf(m, pm[j]);
    red[tid] = m; __syncthreads();
    for (int s = 64; s; s >>= 1) { if (tid < s) red[tid] = fmaxf(red[tid], red[tid + s]); __syncthreads(); }
    float M = red[0]; __syncthreads();
    float se = 0.f;
    for (int j = tid; j < NTILE; j += 128) se += ps[j] * expf(pm[j] - M);
    red[tid] = se; __syncthreads();
    for (int s = 64; s; s >>= 1) { if (tid < s) red[tid] += red[tid + s]; __syncthreads(); }
    if (tid == 0) {
        float lse = M + logf(red[0]);
        int l = lab[r];
        g_nll[r] = (l > 0) ? (lse - g_lab[r]) : 0.f;
    }
}

__global__ void loss_final_kernel(const int* __restrict__ lab, float* __restrict__ out)
{
    __shared__ float red[64];
    const int b = threadIdx.x;
    float s = 0.f, cnt = 0.f;
    for (int t = 0; t < TT; t++) {
        int r = b * TT + t;
        s += g_nll[r];
        cnt += (lab[r] > 0) ? 1.f : 0.f;
    }
    red[b] = s / (cnt + 1e-6f);
    __syncthreads();
    if (b == 0) {
        float a = 0.f;
        for (int i = 0; i < 64; i++) a += red[i];
        out[0] = a / 64.f;
    }
}

// ---------------- host launcher ----------------
extern "C" void kernel_launch(void* const* d_in, const int* in_sizes, int n_in,
                              void* d_out, int out_size)
{
    const float* encode_hidden = (const float*)d_in[0];
    const float* encode_output = (const float*)d_in[1];
    const int*   seq_label     = (const int*)  d_in[3];
    const int*   decoder_input = (const int*)  d_in[4];
    const float* style_emb     = (const float*)d_in[5];
    const float* w_e2d         = (const float*)d_in[6];
    const float* b_e2d         = (const float*)d_in[7];
    const float* attn_W        = (const float*)d_in[8];
    const float* emb_table     = (const float*)d_in[9];
    const float* w_ih          = (const float*)d_in[10];
    const float* w_hh          = (const float*)d_in[11];
    const float* b_ih          = (const float*)d_in[12];
    const float* b_hh          = (const float*)d_in[13];
    const float* proj_w        = (const float*)d_in[14];
    const float* proj_b        = (const float*)d_in[15];
    float* out = (float*)d_out;

    float *p_cat, *p_inp2, *p_gates, *p_emb, *p_xproj, *p_wcomb, *p_biassum, *p_E2;
    cudaGetSymbolAddress((void**)&p_cat,     g_cat);
    cudaGetSymbolAddress((void**)&p_inp2,    g_inp2);
    cudaGetSymbolAddress((void**)&p_gates,   g_gates);
    cudaGetSymbolAddress((void**)&p_emb,     g_emb);
    cudaGetSymbolAddress((void**)&p_xproj,   g_xproj);
    cudaGetSymbolAddress((void**)&p_wcomb,   g_wcomb);
    cudaGetSymbolAddress((void**)&p_biassum, g_biassum);
    cudaGetSymbolAddress((void**)&p_E2,      g_E2);

    // one-time prep
    prep_small_kernel<<<424, 256>>>(encode_hidden, style_emb, b_ih, b_hh);
    wcomb_kernel<<<2048, 1024>>>(w_ih, w_hh);
    embed_kernel<<<BT, 512>>>(decoder_input, emb_table);

    // h0 = cat @ W_e2d^T + b  -> h half of inp2
    gemm_kernel<false><<<dim3(8, 1, 1), 256>>>(640,
        p_cat, 640, w_e2d, 640, p_inp2 + 512, 1024, b_e2d, nullptr, 0);

    // xproj = emb @ W_ih_emb^T + (b_ih + b_hh)
    gemm_kernel<false><<<dim3(32, 21, 1), 256>>>(512,
        p_emb, 512, w_ih + 512, 1024, p_xproj, 2048, p_biassum, nullptr, 0);

    // E2 = enc @ attn_W^T
    gemm_kernel<false><<<dim3(8, 64, 1), 256>>>(512,
        encode_output, 512, attn_W, 512, p_E2, 512, nullptr, nullptr, 0);

    for (int t = 0; t < TT; t++) {
        pwattn_kernel<<<64, 256>>>(encode_output, t);
        // gates += [ctx|h] @ [W_ih_ctx|W_hh]^T  (split-K atomic; pre-inited = xproj[t])
        gemm_kernel<true><<<dim3(32, 1, 4), 256>>>(256,
            p_inp2, 1024, p_wcomb, 1024, p_gates, 2048, nullptr, nullptr, 0);
    }
    pw_final_kernel<<<64, 512>>>();

    // loss
    lablogit_kernel<<<168, 256>>>(seq_label, proj_w, proj_b);
    proj_lse_kernel<<<dim3(NTILE, 21), 256>>>(proj_w, proj_b);
    loss_row_kernel<<<BT, 128>>>(seq_label);
    loss_final_kernel<<<1, 64>>>(seq_label, out);
}

// round 9
// speedup vs baseline: 2.4297x; 2.4297x over previous
#include <cuda_runtime.h>
#include <cuda_bf16.h>
#include <cstdint>
#include <math.h>

// Problem constants
#define BB 64
#define SS 64
#define TT 21
#define DD 512
#define VV 32000
#define BT (BB*TT)        // 1344
#define NT2 250           // N tiles of 128 for projection
#define MT128 11          // ceil(1344/128)
#define MT16 88           // 1408/16 m-frag tiles
#define KT16 32           // 512/16 k-steps

// ---------------- static device scratch ----------------
__device__ float g_cat[BB*640];
__device__ float g_inp2[BB*1024];      // [context | h]
__device__ float g_gates[BB*2048];
__device__ float g_c[BB*512];
__device__ float g_emb[BT*512];
__device__ float g_xproj[BT*2048];
__device__ float g_wcomb[2048*1024];   // [W_ih_ctx | W_hh]
__device__ float g_biassum[2048];
__device__ float g_E2[BB*SS*512];      // enc @ attn_W^T
__device__ float g_outs[BT*512];
__device__ uint4 g_afrag[MT16*KT16*32];        // A fragments (bf16 pairs)
__device__ uint4 g_bfrag[(VV/16)*KT16*32];     // B fragments, n-tile pairs
__device__ float g_pmax[BT*NT2];
__device__ float g_psum[BT*NT2];
__device__ float g_lab[BT];
__device__ float g_nll[BT];

// ---------------- packed f32x2 helpers (kept for small GEMMs, R5-best) ----------------
__device__ __forceinline__ double pk2(float lo, float hi) {
    double d;
    asm("mov.b64 %0, {%1, %2};" : "=d"(d) : "f"(lo), "f"(hi));
    return d;
}
__device__ __forceinline__ void upk2(double v, float& lo, float& hi) {
    asm("mov.b64 {%0, %1}, %2;" : "=f"(lo), "=f"(hi) : "d"(v));
}
__device__ __forceinline__ void fma2(double& d, double a, double b) {
    asm("fma.rn.f32x2 %0, %1, %2, %0;" : "+d"(d) : "d"(a), "d"(b));
}

// ---------------- generic tiled fp32 GEMM (R5 version, best known) ----------------
template<bool TRANSB, bool ATOMIC>
__global__ void gemm_kernel(int klen,
                            const float* __restrict__ A, int lda,
                            const float* __restrict__ B, int ldb,
                            float* __restrict__ C, int ldc,
                            const float* __restrict__ bias,
                            const float* __restrict__ addf, int ldd)
{
    __shared__ float As[32][68];
    __shared__ float Bs[32][68];
    const int bm = blockIdx.y * 64;
    const int bn = blockIdx.x * 64;
    const int kbeg = blockIdx.z * klen;
    const int tid = threadIdx.x;
    const int tm = (tid >> 4) << 2;
    const int tn = (tid & 15) << 2;
    double acc2[4][2] = {};

    for (int k0 = kbeg; k0 < kbeg + klen; k0 += 32) {
#pragma unroll
        for (int i = 0; i < 8; i++) {
            int e = tid + i * 256;
            int m = e >> 5, k = e & 31;
            As[k][m] = A[(size_t)(bm + m) * lda + k0 + k];
        }
        if (TRANSB) {
#pragma unroll
            for (int i = 0; i < 8; i++) {
                int e = tid + i * 256;
                int n = e >> 5, k = e & 31;
                Bs[k][n] = B[(size_t)(bn + n) * ldb + k0 + k];
            }
        } else {
#pragma unroll
            for (int i = 0; i < 8; i++) {
                int e = tid + i * 256;
                int k = e >> 6, n = e & 63;
                Bs[k][n] = B[(size_t)(k0 + k) * ldb + bn + n];
            }
        }
        __syncthreads();
#pragma unroll
        for (int k = 0; k < 32; k++) {
            float4 av = *reinterpret_cast<const float4*>(&As[k][tm]);
            float4 bv = *reinterpret_cast<const float4*>(&Bs[k][tn]);
            double b01 = pk2(bv.x, bv.y), b23 = pk2(bv.z, bv.w);
            double a0 = pk2(av.x, av.x), a1 = pk2(av.y, av.y);
            double a2 = pk2(av.z, av.z), a3 = pk2(av.w, av.w);
            fma2(acc2[0][0], a0, b01); fma2(acc2[0][1], a0, b23);
            fma2(acc2[1][0], a1, b01); fma2(acc2[1][1], a1, b23);
            fma2(acc2[2][0], a2, b01); fma2(acc2[2][1], a2, b23);
            fma2(acc2[3][0], a3, b01); fma2(acc2[3][1], a3, b23);
        }
        __syncthreads();
    }

    float acc[4][4];
#pragma unroll
    for (int i = 0; i < 4; i++) {
        upk2(acc2[i][0], acc[i][0], acc[i][1]);
        upk2(acc2[i][1], acc[i][2], acc[i][3]);
    }

    if (ATOMIC) {
#pragma unroll
        for (int i = 0; i < 4; i++) {
            size_t ro = (size_t)(bm + tm + i);
#pragma unroll
            for (int j = 0; j < 4; j++)
                atomicAdd(&C[ro * ldc + bn + tn + j], acc[i][j]);
        }
    } else {
#pragma unroll
        for (int i = 0; i < 4; i++) {
            size_t ro = (size_t)(bm + tm + i);
#pragma unroll
            for (int j = 0; j < 4; j++) {
                float v = acc[i][j];
                int n = bn + tn + j;
                if (bias) v += bias[n];
                if (addf) v += addf[ro * ldd + n];
                C[ro * ldc + n] = v;
            }
        }
    }
}

// ---------------- bf16 helpers ----------------
__device__ __forceinline__ unsigned pkbf(float lo, float hi) {
    __nv_bfloat162 h = __floats2bfloat162_rn(lo, hi);
    return *reinterpret_cast<unsigned*>(&h);
}

__device__ __forceinline__ void mma_bf16(float* d,
    unsigned a0, unsigned a1, unsigned a2, unsigned a3,
    unsigned b0, unsigned b1)
{
    asm volatile(
        "mma.sync.aligned.m16n8k16.row.col.f32.bf16.bf16.f32 "
        "{%0,%1,%2,%3},{%4,%5,%6,%7},{%8,%9},{%0,%1,%2,%3};\n"
        : "+f"(d[0]), "+f"(d[1]), "+f"(d[2]), "+f"(d[3])
        : "r"(a0), "r"(a1), "r"(a2), "r"(a3), "r"(b0), "r"(b1));
}

// ---------------- fragment conversion kernels ----------------
// A fragments: mt in [0,88), kt in [0,32), lane -> uint4 {a0,a1,a2,a3}
// a0=(r=mt*16+gid, c=kt*16+tig*2), a1=(r+8, c), a2=(r, c+8), a3=(r+8, c+8)
__global__ void conv_afrag_kernel()
{
    int gt = blockIdx.x * 256 + threadIdx.x;      // 88*32*32 = 90112
    if (gt >= MT16 * KT16 * 32) return;
    int lane = gt & 31;
    int kt = (gt >> 5) & 31;
    int mt = gt >> 10;
    int gid = lane >> 2, tig = lane & 3;
    int r0 = mt * 16 + gid, r1 = r0 + 8;
    int c0 = kt * 16 + tig * 2;
    const float* A = g_outs;
    uint4 v;
    v.x = (r0 < BT) ? pkbf(A[(size_t)r0*512 + c0],     A[(size_t)r0*512 + c0 + 1]) : 0u;
    v.y = (r1 < BT) ? pkbf(A[(size_t)r1*512 + c0],     A[(size_t)r1*512 + c0 + 1]) : 0u;
    v.z = (r0 < BT) ? pkbf(A[(size_t)r0*512 + c0 + 8], A[(size_t)r0*512 + c0 + 9]) : 0u;
    v.w = (r1 < BT) ? pkbf(A[(size_t)r1*512 + c0 + 8], A[(size_t)r1*512 + c0 + 9]) : 0u;
    g_afrag[(mt * KT16 + kt) * 32 + lane] = v;
}

// B fragments: nt2 in [0,2000) (pair of 8-col n-tiles), kt, lane -> uint4
// {b0(nt even), b1(nt even), b0(nt odd), b1(nt odd)}
// b0=(k=kt*16+tig*2 pair, n=nt*8+gid), b1=(k+8 pair)
__global__ void conv_bfrag_kernel(const float* __restrict__ W)
{
    int gt = blockIdx.x * 256 + threadIdx.x;      // 2000*32*32 = 2.048M
    int lane = gt & 31;
    int kt = (gt >> 5) & 31;
    int nt2 = gt >> 10;
    if (nt2 >= VV / 16) return;
    int gid = lane >> 2, tig = lane & 3;
    int k0 = kt * 16 + tig * 2;
    int n0 = (nt2 * 2) * 8 + gid;
    int n1 = (nt2 * 2 + 1) * 8 + gid;
    const float* w0 = W + (size_t)n0 * 512;
    const float* w1 = W + (size_t)n1 * 512;
    uint4 v;
    v.x = pkbf(w0[k0],     w0[k0 + 1]);
    v.y = pkbf(w0[k0 + 8], w0[k0 + 9]);
    v.z = pkbf(w1[k0],     w1[k0 + 1]);
    v.w = pkbf(w1[k0 + 8], w1[k0 + 9]);
    g_bfrag[(nt2 * KT16 + kt) * 32 + lane] = v;
}

// ---------------- HMMA projection GEMM + fused logsumexp ----------------
// CTA: 128(m) x 128(n), 8 warps (4m x 2n), warp = 32x64 via m16n8k16.
__global__ void __launch_bounds__(256)
proj_hmma_kernel(const uint4* __restrict__ Af, const uint4* __restrict__ Bf,
                 const float* __restrict__ pb)
{
    __shared__ float sb[128];
    __shared__ float smax[2][128], ssum[2][128];
    const int tid = threadIdx.x, lane = tid & 31, wid = tid >> 5;
    const int wm = wid >> 1, wn = wid & 1;
    const int gid = lane >> 2, tig = lane & 3;
    const int nb = blockIdx.x, mb = blockIdx.y;

    if (tid < 128) sb[tid] = pb[nb * 128 + tid];

    const int mt0 = mb * 8 + wm * 2;              // two m-frag tiles: mt0, mt0+1
    const uint4* a0p = Af + (size_t)(mt0 * KT16) * 32 + lane;
    const uint4* a1p = Af + (size_t)((mt0 + 1) * KT16) * 32 + lane;
    const int nt2b = nb * 8 + wn * 4;             // four n-tile pairs
    const uint4* bp0 = Bf + (size_t)((nt2b + 0) * KT16) * 32 + lane;
    const uint4* bp1 = Bf + (size_t)((nt2b + 1) * KT16) * 32 + lane;
    const uint4* bp2 = Bf + (size_t)((nt2b + 2) * KT16) * 32 + lane;
    const uint4* bp3 = Bf + (size_t)((nt2b + 3) * KT16) * 32 + lane;

    float acc[2][8][4] = {};

#pragma unroll 4
    for (int kt = 0; kt < KT16; kt++) {
        uint4 av0 = a0p[kt * 32];
        uint4 av1 = a1p[kt * 32];
        uint4 bv0 = bp0[kt * 32];
        uint4 bv1 = bp1[kt * 32];
        uint4 bv2 = bp2[kt * 32];
        uint4 bv3 = bp3[kt * 32];

        mma_bf16(acc[0][0], av0.x, av0.y, av0.z, av0.w, bv0.x, bv0.y);
        mma_bf16(acc[0][1], av0.x, av0.y, av0.z, av0.w, bv0.z, bv0.w);
        mma_bf16(acc[0][2], av0.x, av0.y, av0.z, av0.w, bv1.x, bv1.y);
        mma_bf16(acc[0][3], av0.x, av0.y, av0.z, av0.w, bv1.z, bv1.w);
        mma_bf16(acc[0][4], av0.x, av0.y, av0.z, av0.w, bv2.x, bv2.y);
        mma_bf16(acc[0][5], av0.x, av0.y, av0.z, av0.w, bv2.z, bv2.w);
        mma_bf16(acc[0][6], av0.x, av0.y, av0.z, av0.w, bv3.x, bv3.y);
        mma_bf16(acc[0][7], av0.x, av0.y, av0.z, av0.w, bv3.z, bv3.w);
        mma_bf16(acc[1][0], av1.x, av1.y, av1.z, av1.w, bv0.x, bv0.y);
        mma_bf16(acc[1][1], av1.x, av1.y, av1.z, av1.w, bv0.z, bv0.w);
        mma_bf16(acc[1][2], av1.x, av1.y, av1.z, av1.w, bv1.x, bv1.y);
        mma_bf16(acc[1][3], av1.x, av1.y, av1.z, av1.w, bv1.z, bv1.w);
        mma_bf16(acc[1][4], av1.x, av1.y, av1.z, av1.w, bv2.x, bv2.y);
        mma_bf16(acc[1][5], av1.x, av1.y, av1.z, av1.w, bv2.z, bv2.w);
        mma_bf16(acc[1][6], av1.x, av1.y, av1.z, av1.w, bv3.x, bv3.y);
        mma_bf16(acc[1][7], av1.x, av1.y, av1.z, av1.w, bv3.z, bv3.w);
    }
    __syncthreads();   // sb ready (and reuse barrier)

    // epilogue: bias + per-row max/sumexp; row layout:
    // rowl = wm*32 + f*16 + half*8 + gid; cols = wn*64 + nf*8 + tig*2 + {0,1}
#pragma unroll
    for (int f = 0; f < 2; f++) {
#pragma unroll
        for (int half = 0; half < 2; half++) {
            float v[16];
#pragma unroll
            for (int nf = 0; nf < 8; nf++) {
                float b0 = sb[wn * 64 + nf * 8 + tig * 2];
                float b1 = sb[wn * 64 + nf * 8 + tig * 2 + 1];
                v[nf * 2]     = acc[f][nf][half * 2]     + b0;
                v[nf * 2 + 1] = acc[f][nf][half * 2 + 1] + b1;
            }
            float mx = v[0];
#pragma unroll
            for (int i = 1; i < 16; i++) mx = fmaxf(mx, v[i]);
            mx = fmaxf(mx, __shfl_xor_sync(0xffffffffu, mx, 1));
            mx = fmaxf(mx, __shfl_xor_sync(0xffffffffu, mx, 2));
            float se = 0.f;
#pragma unroll
            for (int i = 0; i < 16; i++) se += expf(v[i] - mx);
            se += __shfl_xor_sync(0xffffffffu, se, 1);
            se += __shfl_xor_sync(0xffffffffu, se, 2);
            if (tig == 0) {
                int rowl = wm * 32 + f * 16 + half * 8 + gid;
                smax[wn][rowl] = mx;
                ssum[wn][rowl] = se;
            }
        }
    }
    __syncthreads();

    if (tid < 128) {
        int row = mb * 128 + tid;
        if (row < BT) {
            float m0 = smax[0][tid], m1 = smax[1][tid];
            float M = fmaxf(m0, m1);
            float S = ssum[0][tid] * expf(m0 - M) + ssum[1][tid] * expf(m1 - M);
            g_pmax[(size_t)row * NT2 + nb] = M;
            g_psum[(size_t)row * NT2 + nb] = S;
        }
    }
}

// ---------------- fused pointwise(t-1) + attention(t) ----------------
__global__ void pwattn_kernel(const float* __restrict__ enc, int t)
{
    __shared__ float hs[512];
    __shared__ float sc[64];
    __shared__ float s_inv;
    const int b = blockIdx.x, tid = threadIdx.x;

    if (t > 0) {
        const int gb = b * 2048;
#pragma unroll
        for (int u = 0; u < 2; u++) {
            int j = tid + u * 256;
            float gi = g_gates[gb + j];
            float gf = g_gates[gb + 512 + j];
            float gg = g_gates[gb + 1024 + j];
            float go = g_gates[gb + 1536 + j];
            float c = g_c[b * 512 + j];
            float si = 1.f / (1.f + expf(-gi));
            float sf = 1.f / (1.f + expf(-gf));
            float so = 1.f / (1.f + expf(-go));
            c = sf * c + si * tanhf(gg);
            g_c[b * 512 + j] = c;
            float h = so * tanhf(c);
            g_outs[(size_t)(b * TT + (t - 1)) * 512 + j] = h;
            g_inp2[b * 1024 + 512 + j] = h;
            hs[j] = h;
        }
    } else {
        hs[tid]       = g_inp2[b * 1024 + 512 + tid];
        hs[tid + 256] = g_inp2[b * 1024 + 768 + tid];
    }
    __syncthreads();

    // init gates = xproj[:, t, :] for the split-K atomic GEMM
    {
        size_t xo = (size_t)(b * TT + t) * 2048;
#pragma unroll
        for (int i = 0; i < 8; i++)
            g_gates[b * 2048 + tid + i * 256] = g_xproj[xo + tid + i * 256];
    }

    const int w = tid >> 5, lane = tid & 31;
    const float* E2b = g_E2 + (size_t)b * SS * 512;
    for (int s = w; s < SS; s += 8) {
        const float* er = E2b + (size_t)s * 512;
        float a = 0.f;
        for (int k = lane; k < 512; k += 32) a += hs[k] * er[k];
#pragma unroll
        for (int o = 16; o; o >>= 1) a += __shfl_xor_sync(0xffffffffu, a, o);
        if (lane == 0) sc[s] = a;
    }
    __syncthreads();

    if (w == 0) {
        float v0 = sc[lane], v1 = sc[lane + 32];
        float m = fmaxf(v0, v1);
#pragma unroll
        for (int o = 16; o; o >>= 1) m = fmaxf(m, __shfl_xor_sync(0xffffffffu, m, o));
        float e0 = expf(v0 - m), e1 = expf(v1 - m);
        float ssm = e0 + e1;
#pragma unroll
        for (int o = 16; o; o >>= 1) ssm += __shfl_xor_sync(0xffffffffu, ssm, o);
        sc[lane] = e0; sc[lane + 32] = e1;
        if (lane == 0) s_inv = 1.f / ssm;
    }
    __syncthreads();

    float inv = s_inv;
    const float* eb = enc + (size_t)b * SS * DD;
    for (int d = tid; d < DD; d += 256) {
        float a = 0.f;
#pragma unroll 8
        for (int s = 0; s < SS; s++) a += sc[s] * eb[(size_t)s * DD + d];
        g_inp2[b * 1024 + d] = a * inv;
    }
}

// final pointwise (produces outs[T-1])
__global__ void pw_final_kernel()
{
    const int b = blockIdx.x, j = threadIdx.x;
    const int gb = b * 2048;
    float gi = g_gates[gb + j];
    float gf = g_gates[gb + 512 + j];
    float gg = g_gates[gb + 1024 + j];
    float go = g_gates[gb + 1536 + j];
    float c = g_c[b * 512 + j];
    float si = 1.f / (1.f + expf(-gi));
    float sf = 1.f / (1.f + expf(-gf));
    float so = 1.f / (1.f + expf(-go));
    c = sf * c + si * tanhf(gg);
    float h = so * tanhf(c);
    g_outs[(size_t)(b * TT + TT - 1) * 512 + j] = h;
}

// ---------------- one-time prep ----------------
__global__ void prep_small_kernel(const float* __restrict__ eh, const float* __restrict__ st,
                                  const float* __restrict__ bih, const float* __restrict__ bhh)
{
    int i = blockIdx.x * blockDim.x + threadIdx.x;
    if (i < BB * 640) {
        int b = i / 640, j = i - b * 640;
        g_cat[i] = (j < 512) ? eh[b * 512 + j] : st[b * 512 + 384 + (j - 512)];
    } else if (i < BB * 640 + 2048) {
        int j = i - BB * 640;
        g_biassum[j] = bih[j] + bhh[j];
    } else if (i < BB * 640 + 2048 + BB * 512) {
        g_c[i - (BB * 640 + 2048)] = 0.f;
    }
}

__global__ void wcomb_kernel(const float* __restrict__ wih, const float* __restrict__ whh)
{
    int i = blockIdx.x * blockDim.x + threadIdx.x;
    int r = i >> 10, c = i & 1023;
    g_wcomb[i] = (c < 512) ? wih[(size_t)r * 1024 + c] : whh[(size_t)r * 512 + (c - 512)];
}

__global__ void embed_kernel(const int* __restrict__ di, const float* __restrict__ et)
{
    int row = blockIdx.x, tid = threadIdx.x;
    int idx = di[row];
    g_emb[(size_t)row * 512 + tid] = et[(size_t)idx * 512 + tid];
}

// ---------------- loss ----------------
__global__ void lablogit_kernel(const int* __restrict__ lab, const float* __restrict__ pw,
                                const float* __restrict__ pb)
{
    int gt = blockIdx.x * blockDim.x + threadIdx.x;
    int w = gt >> 5, lane = gt & 31;
    if (w >= BT) return;
    int l = lab[w];
    const float* o  = g_outs + (size_t)w * 512;
    const float* wr = pw + (size_t)l * 512;
    float a = 0.f;
    for (int k = lane; k < 512; k += 32) a += o[k] * wr[k];
#pragma unroll
    for (int off = 16; off; off >>= 1) a += __shfl_xor_sync(0xffffffffu, a, off);
    if (lane == 0) g_lab[w] = a + pb[l];
}

__global__ void loss_row_kernel(const int* __restrict__ lab)
{
    __shared__ float red[128];
    const int r = blockIdx.x, tid = threadIdx.x;
    const float* pm = g_pmax + (size_t)r * NT2;
    const float* ps = g_psum + (size_t)r * NT2;
    float m = -1e30f;
    for (int j = tid; j < NT2; j += 128) m = fmaxf(m, pm[j]);
    red[tid] = m; __syncthreads();
    for (int s = 64; s; s >>= 1) { if (tid < s) red[tid] = fmaxf(red[tid], red[tid + s]); __syncthreads(); }
    float M = red[0]; __syncthreads();
    float se = 0.f;
    for (int j = tid; j < NT2; j += 128) se += ps[j] * expf(pm[j] - M);
    red[tid] = se; __syncthreads();
    for (int s = 64; s; s >>= 1) { if (tid < s) red[tid] += red[tid + s]; __syncthreads(); }
    if (tid == 0) {
        float lse = M + logf(red[0]);
        int l = lab[r];
        g_nll[r] = (l > 0) ? (lse - g_lab[r]) : 0.f;
    }
}

__global__ void loss_final_kernel(const int* __restrict__ lab, float* __restrict__ out)
{
    __shared__ float red[64];
    const int b = threadIdx.x;
    float s = 0.f, cnt = 0.f;
    for (int t = 0; t < TT; t++) {
        int r = b * TT + t;
        s += g_nll[r];
        cnt += (lab[r] > 0) ? 1.f : 0.f;
    }
    red[b] = s / (cnt + 1e-6f);
    __syncthreads();
    if (b == 0) {
        float a = 0.f;
        for (int i = 0; i < 64; i++) a += red[i];
        out[0] = a / 64.f;
    }
}

// ---------------- host launcher ----------------
extern "C" void kernel_launch(void* const* d_in, const int* in_sizes, int n_in,
                              void* d_out, int out_size)
{
    const float* encode_hidden = (const float*)d_in[0];
    const float* encode_output = (const float*)d_in[1];
    const int*   seq_label     = (const int*)  d_in[3];
    const int*   decoder_input = (const int*)  d_in[4];
    const float* style_emb     = (const float*)d_in[5];
    const float* w_e2d         = (const float*)d_in[6];
    const float* b_e2d         = (const float*)d_in[7];
    const float* attn_W        = (const float*)d_in[8];
    const float* emb_table     = (const float*)d_in[9];
    const float* w_ih          = (const float*)d_in[10];
    const float* w_hh          = (const float*)d_in[11];
    const float* b_ih          = (const float*)d_in[12];
    const float* b_hh          = (const float*)d_in[13];
    const float* proj_w        = (const float*)d_in[14];
    const float* proj_b        = (const float*)d_in[15];
    float* out = (float*)d_out;

    float *p_cat, *p_inp2, *p_gates, *p_emb, *p_xproj, *p_wcomb, *p_biassum, *p_E2;
    uint4 *p_afrag, *p_bfrag;
    cudaGetSymbolAddress((void**)&p_cat,     g_cat);
    cudaGetSymbolAddress((void**)&p_inp2,    g_inp2);
    cudaGetSymbolAddress((void**)&p_gates,   g_gates);
    cudaGetSymbolAddress((void**)&p_emb,     g_emb);
    cudaGetSymbolAddress((void**)&p_xproj,   g_xproj);
    cudaGetSymbolAddress((void**)&p_wcomb,   g_wcomb);
    cudaGetSymbolAddress((void**)&p_biassum, g_biassum);
    cudaGetSymbolAddress((void**)&p_E2,      g_E2);
    cudaGetSymbolAddress((void**)&p_afrag,   g_afrag);
    cudaGetSymbolAddress((void**)&p_bfrag,   g_bfrag);

    // one-time prep
    prep_small_kernel<<<424, 256>>>(encode_hidden, style_emb, b_ih, b_hh);
    wcomb_kernel<<<2048, 1024>>>(w_ih, w_hh);
    embed_kernel<<<BT, 512>>>(decoder_input, emb_table);
    conv_bfrag_kernel<<<8000, 256>>>(proj_w);   // depends only on proj_w

    // h0 = cat @ W_e2d^T + b  -> h half of inp2
    gemm_kernel<true, false><<<dim3(8, 1, 1), 256>>>(640,
        p_cat, 640, w_e2d, 640, p_inp2 + 512, 1024, b_e2d, nullptr, 0);

    // xproj = emb @ W_ih_emb^T + (b_ih + b_hh)
    gemm_kernel<true, false><<<dim3(32, 21, 1), 256>>>(512,
        p_emb, 512, w_ih + 512, 1024, p_xproj, 2048, p_biassum, nullptr, 0);

    // E2 = enc @ attn_W^T
    gemm_kernel<true, false><<<dim3(8, 64, 1), 256>>>(512,
        encode_output, 512, attn_W, 512, p_E2, 512, nullptr, nullptr, 0);

    for (int t = 0; t < TT; t++) {
        pwattn_kernel<<<64, 256>>>(encode_output, t);
        gemm_kernel<true, true><<<dim3(32, 1, 4), 256>>>(256,
            p_inp2, 1024, p_wcomb, 1024, p_gates, 2048, nullptr, nullptr, 0);
    }
    pw_final_kernel<<<64, 512>>>();

    // loss
    conv_afrag_kernel<<<352, 256>>>();
    lablogit_kernel<<<168, 256>>>(seq_label, proj_w, proj_b);
    proj_hmma_kernel<<<dim3(NT2, MT128), 256>>>(p_afrag, p_bfrag, proj_b);
    loss_row_kernel<<<BT, 128>>>(seq_label);
    loss_final_kernel<<<1, 64>>>(seq_label, out);
}